// round 9
// baseline (speedup 1.0000x reference)
#include <cuda_runtime.h>
#include <cuda_bf16.h>
#include <cstdint>

// out[b, p*64+m] = w[p,1]*S_b + (w[p,0]-w[p,1])*x[b,m],  S_b = sum_n x[b,n]
// (indices = 1 - eye(64) collapses the einsum to rank-1 + diagonal correction)
//
// HBM-bound: 64 MB read + 512 MB write, pinned ~6.1 TB/s across R4-R8.
// R9: single-wave persistent launch — 512 CTAs x 512 thr = 8192 warps, ALL
// resident (chip holds ~9472), zero wave transitions. Each warp loops over 32
// rows (warp-strided), identical per-iteration coalescing to the R6 body; the
// loop self-pipelines (next LDG issues while prior stores drain) without R5's
// front-batched-MLP spread penalty.

__global__ __launch_bounds__(512) void perm_closed_kernel(
    const float* __restrict__ x,
    const float* __restrict__ w,
    float* __restrict__ out)
{
    const int warp = (blockIdx.x * (blockDim.x >> 5)) + (threadIdx.x >> 5);
    const int lane = threadIdx.x & 31;
    const int p0   = lane >> 4;
    const int NW   = 8192;               // total warps (512 blocks * 16 warps)

    // Per-warp constants: the 8 w values for p = p0 + 2k (4 pairs), hoisted
    // out of the row loop entirely. w = (8,2) fp32 = 4 float4.
    const float4* __restrict__ w4 = reinterpret_cast<const float4*>(w);
    float dv[4], w1v[4];
    #pragma unroll
    for (int k = 0; k < 4; ++k) {
        const int p = p0 + 2 * k;
        const float4 wp = __ldg(w4 + (p >> 1));
        const float w0 = (p & 1) ? wp.z : wp.x;
        const float w1 = (p & 1) ? wp.w : wp.y;
        dv[k]  = w0 - w1;                // diagonal correction
        w1v[k] = w1;
    }

    const float4* __restrict__ x4 = reinterpret_cast<const float4*>(x);

    // 32 rows per warp, warp-strided so adjacent warps touch adjacent rows
    // every iteration (same coalescing/L2 pattern as the one-shot kernel).
    #pragma unroll 2
    for (int it = 0; it < 32; ++it) {
        const int row = warp + it * NW;

        // x row: 16 float4; 2 lanes share one (coalesced 256B row fetch).
        const float4 xv = x4[(size_t)row * 16 + (lane & 15)];

        // 4-step butterfly within each 16-lane half (each half holds the row).
        float S = (xv.x + xv.y) + (xv.z + xv.w);
        #pragma unroll
        for (int o = 8; o > 0; o >>= 1)
            S += __shfl_xor_sync(0xffffffffu, S, o);

        // Output row = 128 float4. Lane l writes f in {l, l+32, l+64, l+96}:
        //   p = f/16 = p0 + 2k,  m-block = f%16 = lane&15 (matches xv).
        float4* __restrict__ o4 = reinterpret_cast<float4*>(out) + (size_t)row * 128;
        #pragma unroll
        for (int k = 0; k < 4; ++k) {
            const float a = w1v[k] * S;
            float4 r;
            r.x = fmaf(dv[k], xv.x, a);
            r.y = fmaf(dv[k], xv.y, a);
            r.z = fmaf(dv[k], xv.z, a);
            r.w = fmaf(dv[k], xv.w, a);
            o4[lane + 32 * k] = r;
        }
    }
}

extern "C" void kernel_launch(void* const* d_in, const int* in_sizes, int n_in,
                              void* d_out, int out_size)
{
    const float* x = (const float*)d_in[0];   // (B, 64) fp32
    const float* w = (const float*)d_in[1];   // (8, 2)  fp32
    // d_in[2] = indices (64,64) int32 == 1 - eye: structure folded into the math.

    float* out = (float*)d_out;               // (B, 512) fp32
    // B = 262144 rows = 8192 warps * 32 rows/warp, exact.
    perm_closed_kernel<<<512, 512>>>(x, w, out);
}

// round 10
// speedup vs baseline: 1.2306x; 1.2306x over previous
#include <cuda_runtime.h>
#include <cuda_bf16.h>
#include <cstdint>

// out[b, p*64+m] = w[p,1]*S_b + (w[p,0]-w[p,1])*x[b,m],  S_b = sum_n x[b,n]
// (indices = 1 - eye(64) collapses the einsum to rank-1 + diagonal correction)
//
// HBM-bound: 64 MB read + 512 MB write (irreducible), ~6.1 TB/s achieved =
// write-heavy DRAM ceiling. Session evidence:
//   R2  cs hints          : neutral/negative
//   R5  2 rows/warp (MLP2): -2.5% (cross-CTA L1tex queue spread)
//   R8  w-hoist           : neutral (latency already hidden by occupancy)
//   R9  persistent 1-wave : -21% (per-warp serial chain starves request MLP)
// Optimum = one-shot grid, 1 row/warp, 1024-thread blocks, exact grid (R6).
// R10 = R6 restored as the terminal kernel.

__global__ __launch_bounds__(1024) void perm_closed_kernel(
    const float* __restrict__ x,
    const float* __restrict__ w,
    float* __restrict__ out)
{
    const int row  = (blockIdx.x * (blockDim.x >> 5)) + (threadIdx.x >> 5);
    const int lane = threadIdx.x & 31;

    // x row: 16 float4 per row; 2 lanes share one (coalesced 256B row fetch
    // via L1 broadcast).
    const float4* __restrict__ x4 = reinterpret_cast<const float4*>(x) + (size_t)row * 16;
    const float4 xv = x4[lane & 15];

    // Each 16-lane half holds the complete row: 4-step butterfly gives the
    // exact row sum.
    float S = (xv.x + xv.y) + (xv.z + xv.w);
    #pragma unroll
    for (int o = 8; o > 0; o >>= 1)
        S += __shfl_xor_sync(0xffffffffu, S, o);

    // Output row = 128 float4. Lane l writes float4 f in {l, l+32, l+64, l+96}:
    //   p = f/16 = (lane>>4) + 2k,  m-block = f%16 = lane&15  (matches xv).
    float4* __restrict__ o4 = reinterpret_cast<float4*>(out) + (size_t)row * 128;
    const int p0 = lane >> 4;

    #pragma unroll
    for (int k = 0; k < 4; ++k) {
        const int p = p0 + 2 * k;
        const float w0 = __ldg(w + 2 * p);
        const float w1 = __ldg(w + 2 * p + 1);
        const float a = w1 * S;          // coefficient for the row sum
        const float d = w0 - w1;         // diagonal correction
        float4 r;
        r.x = fmaf(d, xv.x, a);
        r.y = fmaf(d, xv.y, a);
        r.z = fmaf(d, xv.z, a);
        r.w = fmaf(d, xv.w, a);
        o4[lane + 32 * k] = r;
    }
}

extern "C" void kernel_launch(void* const* d_in, const int* in_sizes, int n_in,
                              void* d_out, int out_size)
{
    const float* x = (const float*)d_in[0];   // (B, 64) fp32
    const float* w = (const float*)d_in[1];   // (8, 2)  fp32
    // d_in[2] = indices (64,64) int32 == 1 - eye: structure folded into the math.

    float* out = (float*)d_out;               // (B, 512) fp32
    const int B = in_sizes[0] / 64;           // 262144

    const int threads = 1024;                 // 32 warps = 32 rows per block
    const int rows_per_block = threads / 32;
    const int blocks = B / rows_per_block;    // 262144/32 = 8192, exact
    perm_closed_kernel<<<blocks, threads>>>(x, w, out);
}

// round 11
// speedup vs baseline: 1.2454x; 1.0120x over previous
#include <cuda_runtime.h>
#include <cuda_bf16.h>
#include <cstdint>

// out[b, p*64+m] = w[p,1]*S_b + (w[p,0]-w[p,1])*x[b,m],  S_b = sum_n x[b,n]
// (indices = 1 - eye(64) collapses the einsum to rank-1 + diagonal correction,
//  turning a 17-GFLOP einsum into one row-sum + 16 FMAs per output element.)
//
// TERMINAL KERNEL — HBM-bound at the write-heavy DRAM ceiling.
// Traffic: 64 MB read + 512 MB write (irreducible). Achieved: ~6.1 TB/s,
// 77% DRAM, kernel ~89 us. Session evidence (all falsified or neutral):
//   R2 cs hints -, R5 2rows/warp -, R8 w-hoist 0, R9 persistent-wave --.
// Optimum: one-shot grid, 1 row/warp (MLP_p1=1), 1024-thread blocks,
// exact 8192-block grid, no bounds branch, 26 regs.

__global__ __launch_bounds__(1024) void perm_closed_kernel(
    const float* __restrict__ x,
    const float* __restrict__ w,
    float* __restrict__ out)
{
    const int row  = (blockIdx.x * (blockDim.x >> 5)) + (threadIdx.x >> 5);
    const int lane = threadIdx.x & 31;

    // x row: 16 float4 per row; 2 lanes share one (coalesced 256B row fetch
    // via L1 broadcast).
    const float4* __restrict__ x4 = reinterpret_cast<const float4*>(x) + (size_t)row * 16;
    const float4 xv = x4[lane & 15];

    // Each 16-lane half holds the complete row: 4-step butterfly gives the
    // exact row sum.
    float S = (xv.x + xv.y) + (xv.z + xv.w);
    #pragma unroll
    for (int o = 8; o > 0; o >>= 1)
        S += __shfl_xor_sync(0xffffffffu, S, o);

    // Output row = 128 float4. Lane l writes float4 f in {l, l+32, l+64, l+96}:
    //   p = f/16 = (lane>>4) + 2k,  m-block = f%16 = lane&15  (matches xv).
    // Warp writes 4 x 512B fully-covered contiguous spans -> no fetch-on-write.
    float4* __restrict__ o4 = reinterpret_cast<float4*>(out) + (size_t)row * 128;
    const int p0 = lane >> 4;

    #pragma unroll
    for (int k = 0; k < 4; ++k) {
        const int p = p0 + 2 * k;
        const float w0 = __ldg(w + 2 * p);
        const float w1 = __ldg(w + 2 * p + 1);
        const float a = w1 * S;          // coefficient for the row sum
        const float d = w0 - w1;         // diagonal correction
        float4 r;
        r.x = fmaf(d, xv.x, a);
        r.y = fmaf(d, xv.y, a);
        r.z = fmaf(d, xv.z, a);
        r.w = fmaf(d, xv.w, a);
        o4[lane + 32 * k] = r;
    }
}

extern "C" void kernel_launch(void* const* d_in, const int* in_sizes, int n_in,
                              void* d_out, int out_size)
{
    const float* x = (const float*)d_in[0];   // (B, 64) fp32
    const float* w = (const float*)d_in[1];   // (8, 2)  fp32
    // d_in[2] = indices (64,64) int32 == 1 - eye: structure folded into the math.

    float* out = (float*)d_out;               // (B, 512) fp32
    const int B = in_sizes[0] / 64;           // 262144

    const int threads = 1024;                 // 32 warps = 32 rows per block
    const int rows_per_block = threads / 32;
    const int blocks = B / rows_per_block;    // 262144/32 = 8192, exact
    perm_closed_kernel<<<blocks, threads>>>(x, w, out);
}